// round 5
// baseline (speedup 1.0000x reference)
#include <cuda_runtime.h>
#include <cuda_bf16.h>
#include <cstdint>
#include <math.h>

#define B_SZ 16384
#define N_SZ 1024
#define I_SZ 128
#define O_SZ 64
#define REFRACT 0.9f

#define BM 64
#define KC 64
#define NCHUNK 16
#define THREADS 256

// stage layout: A_hi 8K | A_lo 8K | B_hi 8K | B_lo 8K = 32768 bytes
#define STAGE_BYTES 32768
#define OFF_AHI 0
#define OFF_ALO 8192
#define OFF_BHI 16384
#define OFF_BLO 24576
#define OFF_BIAS (2 * STAGE_BYTES)         // 65536
#define OFF_ACT  (OFF_BIAS + 256)
#define SMEM_TOTAL (OFF_ACT + 256)         // 66048

// Prepped weights: W'[n][k] K-major (transposed), refractory folded, bf16 hi/lo
__device__ __align__(16) unsigned short g_Whi[O_SZ * N_SZ];
__device__ __align__(16) unsigned short g_Wlo[O_SZ * N_SZ];
__device__ float g_bias[O_SZ];
__device__ int   g_act[O_SZ];

// ---------------- helpers ----------------
__device__ __forceinline__ uint32_t smem_u32(const void* p) {
    uint32_t a;
    asm("{ .reg .u64 t; cvta.to.shared.u64 t, %1; cvt.u32.u64 %0, t; }"
        : "=r"(a) : "l"(p));
    return a;
}
// packed bf16x2: low half = bf16(lo), high half = bf16(hi)
__device__ __forceinline__ uint32_t pack_bf16(float lo, float hi) {
    uint32_t r;
    asm("cvt.rn.bf16x2.f32 %0, %1, %2;" : "=r"(r) : "f"(hi), "f"(lo));
    return r;
}
__device__ __forceinline__ uint32_t swz(uint32_t off) {
    return off ^ ((off >> 3) & 0x70);
}
__device__ __forceinline__ void ldsm4(uint32_t* r, uint32_t addr) {
    asm volatile("ldmatrix.sync.aligned.m8n8.x4.shared.b16 {%0,%1,%2,%3}, [%4];"
                 : "=r"(r[0]), "=r"(r[1]), "=r"(r[2]), "=r"(r[3]) : "r"(addr));
}
__device__ __forceinline__ void mma16816(float* c, const uint32_t* a,
                                         uint32_t b0, uint32_t b1) {
    asm volatile(
        "mma.sync.aligned.m16n8k16.row.col.f32.bf16.bf16.f32 "
        "{%0,%1,%2,%3}, {%4,%5,%6,%7}, {%8,%9}, {%0,%1,%2,%3};"
        : "+f"(c[0]), "+f"(c[1]), "+f"(c[2]), "+f"(c[3])
        : "r"(a[0]), "r"(a[1]), "r"(a[2]), "r"(a[3]), "r"(b0), "r"(b1));
}
__device__ __forceinline__ float activate(float x, int a) {
    if (a == 0) return fmaxf(x, 0.0f);
    if (a == 1) return tanhf(x);
    if (a == 2) return 1.0f / (1.0f + expf(-x));
    return x;
}

// ---------------- prep ----------------
__global__ void prep_kernel(const float* __restrict__ W,
                            const float* __restrict__ bias,
                            const int* __restrict__ act) {
    int idx = blockIdx.x * blockDim.x + threadIdx.x;
    if (idx < O_SZ * N_SZ) {
        int k = idx >> 6;
        int n = idx & 63;
        float s = (k >= I_SZ && k < (N_SZ - O_SZ)) ? REFRACT : 1.0f;
        float w = W[(size_t)k * N_SZ + (N_SZ - O_SZ) + n] * s;
        uint32_t hp = pack_bf16(w, 0.0f);
        float hf = __uint_as_float(hp << 16);
        uint32_t lp = pack_bf16(w - hf, 0.0f);
        g_Whi[n * N_SZ + k] = (unsigned short)(hp & 0xFFFF);
        g_Wlo[n * N_SZ + k] = (unsigned short)(lp & 0xFFFF);
    }
    if (idx < O_SZ) {
        g_bias[idx] = bias[(N_SZ - O_SZ) + idx];
        g_act[idx]  = act[(N_SZ - O_SZ) + idx];
    }
}

// ---------------- chunk load: gmem -> regs ----------------
// A: 64 rows x 64 f32; thread t covers row t>>2, 16 floats at col (t&3)*16
__device__ __forceinline__ void load_chunk(int i, int t, int m0,
                                           const float* __restrict__ prev,
                                           const float* __restrict__ inp,
                                           float4 (&a)[4], uint4 (&b)[4]) {
    const int k0 = i * KC;
    const int rr = t >> 2;
    const int kf = (t & 3) * 16;
    const float* s = (k0 < I_SZ)
        ? inp  + (size_t)(m0 + rr) * I_SZ + k0 + kf
        : prev + (size_t)(m0 + rr) * N_SZ + k0 + kf;
#pragma unroll
    for (int p = 0; p < 4; p++) a[p] = ((const float4*)s)[p];

#pragma unroll
    for (int p = 0; p < 2; p++) {
        const int slot = p * 256 + t;              // 0..511
        const int n = slot >> 3, u = slot & 7;
        const size_t byt = (size_t)n * 2048 + (size_t)k0 * 2 + (size_t)u * 16;
        b[p]     = *(const uint4*)((const char*)g_Whi + byt);
        b[p + 2] = *(const uint4*)((const char*)g_Wlo + byt);
    }
}

// ---------------- chunk store: regs -> smem (split + swizzle) ----------------
__device__ __forceinline__ void store_chunk(char* base, int t,
                                            const float4 (&a)[4], const uint4 (&b)[4]) {
    const int row = t >> 2;
    const int u4  = t & 3;
#pragma unroll
    for (int h = 0; h < 2; h++) {
        const float4 v0 = a[2 * h], v1 = a[2 * h + 1];
        const uint32_t h0 = pack_bf16(v0.x, v0.y);
        const uint32_t h1 = pack_bf16(v0.z, v0.w);
        const uint32_t h2 = pack_bf16(v1.x, v1.y);
        const uint32_t h3 = pack_bf16(v1.z, v1.w);
        const float r0 = v0.x - __uint_as_float(h0 << 16);
        const float r1 = v0.y - __uint_as_float(h0 & 0xFFFF0000u);
        const float r2 = v0.z - __uint_as_float(h1 << 16);
        const float r3 = v0.w - __uint_as_float(h1 & 0xFFFF0000u);
        const float r4 = v1.x - __uint_as_float(h2 << 16);
        const float r5 = v1.y - __uint_as_float(h2 & 0xFFFF0000u);
        const float r6 = v1.z - __uint_as_float(h3 << 16);
        const float r7 = v1.w - __uint_as_float(h3 & 0xFFFF0000u);
        const uint32_t off = swz((uint32_t)(row * 128 + u4 * 32 + h * 16));
        *(uint4*)(base + OFF_AHI + off) =
            make_uint4(h0, h1, h2, h3);
        *(uint4*)(base + OFF_ALO + off) =
            make_uint4(pack_bf16(r0, r1), pack_bf16(r2, r3),
                       pack_bf16(r4, r5), pack_bf16(r6, r7));
    }
#pragma unroll
    for (int p = 0; p < 2; p++) {
        const int slot = p * 256 + t;
        const int n = slot >> 3, u = slot & 7;
        const uint32_t off = swz((uint32_t)(n * 128 + u * 16));
        *(uint4*)(base + OFF_BHI + off) = b[p];
        *(uint4*)(base + OFF_BLO + off) = b[p + 2];
    }
}

// ---------------- main kernel ----------------
__global__ __launch_bounds__(THREADS, 2)
void mma_kernel(const float* __restrict__ prev,
                const float* __restrict__ inp,
                float* __restrict__ out) {
    extern __shared__ __align__(1024) char smem[];
    const uint32_t sbse = smem_u32(smem);
    const int t = threadIdx.x;
    const int lane = t & 31, wid = t >> 5;
    const int m0 = blockIdx.x * BM;

    if (t < O_SZ) {
        ((float*)(smem + OFF_BIAS))[t] = g_bias[t];
        ((int*)(smem + OFF_ACT))[t]    = g_act[t];
    }

    // warp tiling: 4 M-groups (16 rows) x 2 N-halves (32 cols)
    const int mg = wid >> 1, nh = wid & 1;
    const int lrow = lane & 7, seg = lane >> 3;
    const int arow = mg * 16 + lrow + ((seg & 1) << 3);
    const int akb0 = (seg & 2) << 3;               // 0 or 16 bytes
    const int browb = lrow + ((seg & 2) << 2);     // +8 for seg>=2
    const int bkb0 = (seg & 1) << 4;               // 0 or 16 bytes

    float acc[4][4];
#pragma unroll
    for (int j = 0; j < 4; j++)
#pragma unroll
        for (int c = 0; c < 4; c++) acc[j][c] = 0.0f;

    float4 A[4];
    uint4  Bv[4];
    load_chunk(0, t, m0, prev, inp, A, Bv);
    store_chunk(smem, t, A, Bv);
    __syncthreads();

    for (int i = 0; i < NCHUNK; i++) {
        if (i + 1 < NCHUNK) load_chunk(i + 1, t, m0, prev, inp, A, Bv);

        const uint32_t st = sbse + (uint32_t)((i & 1) * STAGE_BYTES);
#pragma unroll
        for (int s = 0; s < 4; s++) {
            uint32_t ah[4], al[4];
            const uint32_t aoff = swz((uint32_t)(arow * 128 + s * 32 + akb0));
            ldsm4(ah, st + OFF_AHI + aoff);
            ldsm4(al, st + OFF_ALO + aoff);
#pragma unroll
            for (int jj = 0; jj < 2; jj++) {
                uint32_t bh[4], bl[4];
                const uint32_t boff =
                    swz((uint32_t)((nh * 32 + jj * 16 + browb) * 128 + s * 32 + bkb0));
                ldsm4(bh, st + OFF_BHI + boff);
                ldsm4(bl, st + OFF_BLO + boff);
                mma16816(acc[2 * jj],     ah, bh[0], bh[1]);
                mma16816(acc[2 * jj + 1], ah, bh[2], bh[3]);
                mma16816(acc[2 * jj],     ah, bl[0], bl[1]);
                mma16816(acc[2 * jj + 1], ah, bl[2], bl[3]);
                mma16816(acc[2 * jj],     al, bh[0], bh[1]);
                mma16816(acc[2 * jj + 1], al, bh[2], bh[3]);
            }
        }
        if (i + 1 < NCHUNK)
            store_chunk(smem + ((i + 1) & 1) * STAGE_BYTES, t, A, Bv);
        __syncthreads();
    }

    // ---------------- epilogue ----------------
    const float* sbias = (const float*)(smem + OFF_BIAS);
    const int*   sact  = (const int*)(smem + OFF_ACT);
    const int g = lane >> 2, q = lane & 3;
    const int row0 = m0 + mg * 16 + g;
#pragma unroll
    for (int j = 0; j < 4; j++) {
        const int col = nh * 32 + (j >> 1) * 16 + (j & 1) * 8 + q * 2;
        const float b0 = sbias[col], b1 = sbias[col + 1];
        const int   i0 = sact[col],  i1 = sact[col + 1];
        float2 v0, v1;
        v0.x = activate(acc[j][0] + b0, i0);
        v0.y = activate(acc[j][1] + b1, i1);
        v1.x = activate(acc[j][2] + b0, i0);
        v1.y = activate(acc[j][3] + b1, i1);
        *(float2*)(out + (size_t)row0 * O_SZ + col)       = v0;
        *(float2*)(out + (size_t)(row0 + 8) * O_SZ + col) = v1;
    }
}

extern "C" void kernel_launch(void* const* d_in, const int* in_sizes, int n_in,
                              void* d_out, int out_size) {
    const float* prev = (const float*)d_in[0];   // [16384,1024] f32
    const float* inp  = (const float*)d_in[1];   // [16384,128]  f32
    const float* W    = (const float*)d_in[2];   // [1024,1024]  f32
    const float* bias = (const float*)d_in[3];   // [1024]       f32
    const int*   act  = (const int*)d_in[4];     // [1024]       i32
    float* out = (float*)d_out;                  // [16384,64]   f32

    cudaFuncSetAttribute(mma_kernel,
                         cudaFuncAttributeMaxDynamicSharedMemorySize, SMEM_TOTAL);

    prep_kernel<<<(O_SZ * N_SZ + 255) / 256, 256>>>(W, bias, act);
    mma_kernel<<<B_SZ / BM, THREADS, SMEM_TOTAL>>>(prev, inp, out);
}

// round 6
// speedup vs baseline: 1.0039x; 1.0039x over previous
#include <cuda_runtime.h>
#include <cuda_bf16.h>
#include <cstdint>
#include <math.h>

#define B_SZ 16384
#define N_SZ 1024
#define I_SZ 128
#define O_SZ 64
#define REFRACT 0.9f

#define BM 128
#define KC 64
#define NCHUNK 16
#define THREADS 512

// stage: A_hi 16K | A_lo 16K | B_hi 8K | B_lo 8K = 49152
#define STAGE_BYTES 49152
#define OFF_AHI 0
#define OFF_ALO 16384
#define OFF_BHI 32768
#define OFF_BLO 40960
#define OFF_BIAS (2 * STAGE_BYTES)
#define OFF_ACT  (OFF_BIAS + 256)
#define SMEM_TOTAL (OFF_ACT + 256)

// Prepped weights: W'[n][k] K-major (transposed), refractory folded, bf16 hi/lo
__device__ __align__(16) unsigned short g_Whi[O_SZ * N_SZ];
__device__ __align__(16) unsigned short g_Wlo[O_SZ * N_SZ];
__device__ float g_bias[O_SZ];
__device__ int   g_act[O_SZ];

// ---------------- helpers ----------------
__device__ __forceinline__ uint32_t smem_u32(const void* p) {
    uint32_t a;
    asm("{ .reg .u64 t; cvta.to.shared.u64 t, %1; cvt.u32.u64 %0, t; }"
        : "=r"(a) : "l"(p));
    return a;
}
// packed bf16x2: low half = bf16(lo), high half = bf16(hi)
__device__ __forceinline__ uint32_t pack_bf16(float lo, float hi) {
    uint32_t r;
    asm("cvt.rn.bf16x2.f32 %0, %1, %2;" : "=r"(r) : "f"(hi), "f"(lo));
    return r;
}
__device__ __forceinline__ uint32_t swz(uint32_t off) {
    return off ^ ((off >> 3) & 0x70);
}
__device__ __forceinline__ void ldsm4(uint32_t* r, uint32_t addr) {
    asm volatile("ldmatrix.sync.aligned.m8n8.x4.shared.b16 {%0,%1,%2,%3}, [%4];"
                 : "=r"(r[0]), "=r"(r[1]), "=r"(r[2]), "=r"(r[3]) : "r"(addr));
}
__device__ __forceinline__ void mma16816(float* c, const uint32_t* a,
                                         uint32_t b0, uint32_t b1) {
    asm volatile(
        "mma.sync.aligned.m16n8k16.row.col.f32.bf16.bf16.f32 "
        "{%0,%1,%2,%3}, {%4,%5,%6,%7}, {%8,%9}, {%0,%1,%2,%3};"
        : "+f"(c[0]), "+f"(c[1]), "+f"(c[2]), "+f"(c[3])
        : "r"(a[0]), "r"(a[1]), "r"(a[2]), "r"(a[3]), "r"(b0), "r"(b1));
}
__device__ __forceinline__ float activate(float x, int a) {
    if (a == 0) return fmaxf(x, 0.0f);
    if (a == 1) return tanhf(x);
    if (a == 2) return 1.0f / (1.0f + expf(-x));
    return x;
}

// ---------------- prep ----------------
__global__ void prep_kernel(const float* __restrict__ W,
                            const float* __restrict__ bias,
                            const int* __restrict__ act) {
    int idx = blockIdx.x * blockDim.x + threadIdx.x;
    if (idx < O_SZ * N_SZ) {
        int k = idx >> 6;
        int n = idx & 63;
        float s = (k >= I_SZ && k < (N_SZ - O_SZ)) ? REFRACT : 1.0f;
        float w = W[(size_t)k * N_SZ + (N_SZ - O_SZ) + n] * s;
        uint32_t hp = pack_bf16(w, 0.0f);
        float hf = __uint_as_float(hp << 16);
        uint32_t lp = pack_bf16(w - hf, 0.0f);
        g_Whi[n * N_SZ + k] = (unsigned short)(hp & 0xFFFF);
        g_Wlo[n * N_SZ + k] = (unsigned short)(lp & 0xFFFF);
    }
    if (idx < O_SZ) {
        g_bias[idx] = bias[(N_SZ - O_SZ) + idx];
        g_act[idx]  = act[(N_SZ - O_SZ) + idx];
    }
}

// ---------------- chunk load: gmem -> regs ----------------
// A: 128 rows x 64 f32; thread t -> row t>>2, 16 floats at (t&3)*16
// B: 512 uint4 slots per type; thread t -> slot t (n = t>>3, u = t&7)
__device__ __forceinline__ void load_chunk(int i, int t, int m0,
                                           const float* __restrict__ prev,
                                           const float* __restrict__ inp,
                                           float4 (&a)[4], uint4 (&b)[2]) {
    const int k0 = i * KC;
    const int rr = t >> 2;
    const int kf = (t & 3) * 16;
    const float* s = (k0 < I_SZ)
        ? inp  + (size_t)(m0 + rr) * I_SZ + k0 + kf
        : prev + (size_t)(m0 + rr) * N_SZ + k0 + kf;
#pragma unroll
    for (int p = 0; p < 4; p++) a[p] = ((const float4*)s)[p];

    const int n = t >> 3, u = t & 7;
    const size_t byt = (size_t)n * 2048 + (size_t)k0 * 2 + (size_t)u * 16;
    b[0] = *(const uint4*)((const char*)g_Whi + byt);
    b[1] = *(const uint4*)((const char*)g_Wlo + byt);
}

// ---------------- chunk store: regs -> smem (split + swizzle) ----------------
__device__ __forceinline__ void store_chunk(char* base, int t,
                                            const float4 (&a)[4], const uint4 (&b)[2]) {
    const int row = t >> 2;
    const int u4  = t & 3;
#pragma unroll
    for (int h = 0; h < 2; h++) {
        const float4 v0 = a[2 * h], v1 = a[2 * h + 1];
        const uint32_t h0 = pack_bf16(v0.x, v0.y);
        const uint32_t h1 = pack_bf16(v0.z, v0.w);
        const uint32_t h2 = pack_bf16(v1.x, v1.y);
        const uint32_t h3 = pack_bf16(v1.z, v1.w);
        const float r0 = v0.x - __uint_as_float(h0 << 16);
        const float r1 = v0.y - __uint_as_float(h0 & 0xFFFF0000u);
        const float r2 = v0.z - __uint_as_float(h1 << 16);
        const float r3 = v0.w - __uint_as_float(h1 & 0xFFFF0000u);
        const float r4 = v1.x - __uint_as_float(h2 << 16);
        const float r5 = v1.y - __uint_as_float(h2 & 0xFFFF0000u);
        const float r6 = v1.z - __uint_as_float(h3 << 16);
        const float r7 = v1.w - __uint_as_float(h3 & 0xFFFF0000u);
        const uint32_t off = swz((uint32_t)(row * 128 + u4 * 32 + h * 16));
        *(uint4*)(base + OFF_AHI + off) = make_uint4(h0, h1, h2, h3);
        *(uint4*)(base + OFF_ALO + off) =
            make_uint4(pack_bf16(r0, r1), pack_bf16(r2, r3),
                       pack_bf16(r4, r5), pack_bf16(r6, r7));
    }
    {
        const int n = t >> 3, u = t & 7;
        const uint32_t off = swz((uint32_t)(n * 128 + u * 16));
        *(uint4*)(base + OFF_BHI + off) = b[0];
        *(uint4*)(base + OFF_BLO + off) = b[1];
    }
}

// ---------------- main kernel ----------------
__global__ __launch_bounds__(THREADS, 1)
void mma_kernel(const float* __restrict__ prev,
                const float* __restrict__ inp,
                float* __restrict__ out) {
    extern __shared__ __align__(1024) char smem[];
    const uint32_t sbse = smem_u32(smem);
    const int t = threadIdx.x;
    const int lane = t & 31, wid = t >> 5;
    const int m0 = blockIdx.x * BM;

    if (t < O_SZ) {
        ((float*)(smem + OFF_BIAS))[t] = g_bias[t];
        ((int*)(smem + OFF_ACT))[t]    = g_act[t];
    }

    // warp tiling: 8 M-groups (16 rows) x 2 N-halves (32 cols)
    const int mg = wid >> 1, nh = wid & 1;
    const int lrow = lane & 7, seg = lane >> 3;
    const int arow = mg * 16 + lrow + ((seg & 1) << 3);
    const int akb0 = (seg & 2) << 3;               // 0 or 16 bytes
    const int browb = lrow + ((seg & 2) << 2);     // +8 for seg>=2
    const int bkb0 = (seg & 1) << 4;               // 0 or 16 bytes

    float acc[4][4];
#pragma unroll
    for (int j = 0; j < 4; j++)
#pragma unroll
        for (int c = 0; c < 4; c++) acc[j][c] = 0.0f;

    float4 A[4];
    uint4  Bv[2];
    load_chunk(0, t, m0, prev, inp, A, Bv);
    store_chunk(smem, t, A, Bv);
    __syncthreads();

    for (int i = 0; i < NCHUNK; i++) {
        if (i + 1 < NCHUNK) load_chunk(i + 1, t, m0, prev, inp, A, Bv);

        const uint32_t st = sbse + (uint32_t)((i & 1) * STAGE_BYTES);
#pragma unroll
        for (int s = 0; s < 4; s++) {
            uint32_t ah[4], al[4];
            const uint32_t aoff = swz((uint32_t)(arow * 128 + s * 32 + akb0));
            ldsm4(ah, st + OFF_AHI + aoff);
            ldsm4(al, st + OFF_ALO + aoff);
#pragma unroll
            for (int jj = 0; jj < 2; jj++) {
                uint32_t bh[4], bl[4];
                const uint32_t boff =
                    swz((uint32_t)((nh * 32 + jj * 16 + browb) * 128 + s * 32 + bkb0));
                ldsm4(bh, st + OFF_BHI + boff);
                ldsm4(bl, st + OFF_BLO + boff);
                mma16816(acc[2 * jj],     ah, bh[0], bh[1]);
                mma16816(acc[2 * jj + 1], ah, bh[2], bh[3]);
                mma16816(acc[2 * jj],     ah, bl[0], bl[1]);
                mma16816(acc[2 * jj + 1], ah, bl[2], bl[3]);
                mma16816(acc[2 * jj],     al, bh[0], bh[1]);
                mma16816(acc[2 * jj + 1], al, bh[2], bh[3]);
            }
        }
        if (i + 1 < NCHUNK)
            store_chunk(smem + ((i + 1) & 1) * STAGE_BYTES, t, A, Bv);
        __syncthreads();
    }

    // ---------------- epilogue ----------------
    const float* sbias = (const float*)(smem + OFF_BIAS);
    const int*   sact  = (const int*)(smem + OFF_ACT);
    const int g = lane >> 2, q = lane & 3;
    const int row0 = m0 + mg * 16 + g;
#pragma unroll
    for (int j = 0; j < 4; j++) {
        const int col = nh * 32 + (j >> 1) * 16 + (j & 1) * 8 + q * 2;
        const float b0 = sbias[col], b1 = sbias[col + 1];
        const int   i0 = sact[col],  i1 = sact[col + 1];
        float2 v0, v1;
        v0.x = activate(acc[j][0] + b0, i0);
        v0.y = activate(acc[j][1] + b1, i1);
        v1.x = activate(acc[j][2] + b0, i0);
        v1.y = activate(acc[j][3] + b1, i1);
        *(float2*)(out + (size_t)row0 * O_SZ + col)       = v0;
        *(float2*)(out + (size_t)(row0 + 8) * O_SZ + col) = v1;
    }
}

extern "C" void kernel_launch(void* const* d_in, const int* in_sizes, int n_in,
                              void* d_out, int out_size) {
    const float* prev = (const float*)d_in[0];   // [16384,1024] f32
    const float* inp  = (const float*)d_in[1];   // [16384,128]  f32
    const float* W    = (const float*)d_in[2];   // [1024,1024]  f32
    const float* bias = (const float*)d_in[3];   // [1024]       f32
    const int*   act  = (const int*)d_in[4];     // [1024]       i32
    float* out = (float*)d_out;                  // [16384,64]   f32

    cudaFuncSetAttribute(mma_kernel,
                         cudaFuncAttributeMaxDynamicSharedMemorySize, SMEM_TOTAL);

    prep_kernel<<<(O_SZ * N_SZ + 255) / 256, 256>>>(W, bias, act);
    mma_kernel<<<B_SZ / BM, THREADS, SMEM_TOTAL>>>(prev, inp, out);
}

// round 7
// speedup vs baseline: 1.4163x; 1.4109x over previous
#include <cuda_runtime.h>
#include <cuda_fp16.h>
#include <cstdint>
#include <math.h>

#define B_SZ 16384
#define N_SZ 1024
#define I_SZ 128
#define O_SZ 64
#define REFRACT 0.9f

#define BM 64
#define KC 64
#define NCHUNK 16
#define THREADS 256

// stage: A 64x128B = 8K | B 64x128B = 8K
#define STAGE_BYTES 16384
#define OFF_A 0
#define OFF_B 8192
#define OFF_BIAS (2 * STAGE_BYTES)        // 32768
#define OFF_ACT  (OFF_BIAS + 256)
#define SMEM_TOTAL (OFF_ACT + 256)        // 33280

// Prepped weights: W'[n][k] K-major (transposed), refractory folded, fp16
__device__ __align__(16) unsigned short g_Wf16[O_SZ * N_SZ];
__device__ float g_bias[O_SZ];
__device__ int   g_act[O_SZ];

// ---------------- helpers ----------------
__device__ __forceinline__ uint32_t smem_u32(const void* p) {
    uint32_t a;
    asm("{ .reg .u64 t; cvta.to.shared.u64 t, %1; cvt.u32.u64 %0, t; }"
        : "=r"(a) : "l"(p));
    return a;
}
// packed f16x2: low half = f16(lo), high half = f16(hi)
__device__ __forceinline__ uint32_t pack_f16(float lo, float hi) {
    uint32_t r;
    asm("cvt.rn.f16x2.f32 %0, %1, %2;" : "=r"(r) : "f"(hi), "f"(lo));
    return r;
}
__device__ __forceinline__ uint32_t swz(uint32_t off) {
    return off ^ ((off >> 3) & 0x70);
}
__device__ __forceinline__ void ldsm4(uint32_t* r, uint32_t addr) {
    asm volatile("ldmatrix.sync.aligned.m8n8.x4.shared.b16 {%0,%1,%2,%3}, [%4];"
                 : "=r"(r[0]), "=r"(r[1]), "=r"(r[2]), "=r"(r[3]) : "r"(addr));
}
__device__ __forceinline__ void mma16816(float* c, const uint32_t* a,
                                         uint32_t b0, uint32_t b1) {
    asm volatile(
        "mma.sync.aligned.m16n8k16.row.col.f32.f16.f16.f32 "
        "{%0,%1,%2,%3}, {%4,%5,%6,%7}, {%8,%9}, {%0,%1,%2,%3};"
        : "+f"(c[0]), "+f"(c[1]), "+f"(c[2]), "+f"(c[3])
        : "r"(a[0]), "r"(a[1]), "r"(a[2]), "r"(a[3]), "r"(b0), "r"(b1));
}
__device__ __forceinline__ float activate(float x, int a) {
    if (a == 0) return fmaxf(x, 0.0f);
    if (a == 1) return tanhf(x);
    if (a == 2) return 1.0f / (1.0f + expf(-x));
    return x;
}

// ---------------- prep: fold refractory, transpose, fp16 convert ----------------
__global__ void prep_kernel(const float* __restrict__ W,
                            const float* __restrict__ bias,
                            const int* __restrict__ act) {
    int idx = blockIdx.x * blockDim.x + threadIdx.x;   // 65536
    if (idx < O_SZ * N_SZ) {
        int k = idx >> 6;
        int n = idx & 63;
        float s = (k >= I_SZ && k < (N_SZ - O_SZ)) ? REFRACT : 1.0f;
        float w = W[(size_t)k * N_SZ + (N_SZ - O_SZ) + n] * s;
        __half h = __float2half_rn(w);
        g_Wf16[n * N_SZ + k] = __half_as_ushort(h);
    }
    if (idx < O_SZ) {
        g_bias[idx] = bias[(N_SZ - O_SZ) + idx];
        g_act[idx]  = act[(N_SZ - O_SZ) + idx];
    }
}

// ---------------- chunk load: gmem -> regs ----------------
// A: 64 rows x 64 f32; thread t -> row t>>2, 16 floats at (t&3)*16
// B: 64 rows x 64 fp16; 512 uint4 slots; thread t -> slots t, t+256
__device__ __forceinline__ void load_chunk(int i, int t, int m0,
                                           const float* __restrict__ prev,
                                           const float* __restrict__ inp,
                                           float4 (&a)[4], uint4 (&b)[2]) {
    const int k0 = i * KC;
    const int rr = t >> 2;
    const int kf = (t & 3) * 16;
    const float* s = (k0 < I_SZ)
        ? inp  + (size_t)(m0 + rr) * I_SZ + k0 + kf
        : prev + (size_t)(m0 + rr) * N_SZ + k0 + kf;
#pragma unroll
    for (int p = 0; p < 4; p++) a[p] = ((const float4*)s)[p];

#pragma unroll
    for (int p = 0; p < 2; p++) {
        const int slot = p * 256 + t;
        const int n = slot >> 3, u = slot & 7;
        b[p] = *(const uint4*)((const char*)g_Wf16 +
                               (size_t)n * 2048 + (size_t)k0 * 2 + (size_t)u * 16);
    }
}

// ---------------- chunk store: regs -> smem (fp16 convert + swizzle) ----------------
__device__ __forceinline__ void store_chunk(char* base, int t,
                                            const float4 (&a)[4], const uint4 (&b)[2]) {
    const int row = t >> 2;
    const int u4  = t & 3;
    uint32_t h[8];
#pragma unroll
    for (int p = 0; p < 4; p++) {
        h[2 * p]     = pack_f16(a[p].x, a[p].y);
        h[2 * p + 1] = pack_f16(a[p].z, a[p].w);
    }
    const uint32_t o0 = swz((uint32_t)(row * 128 + u4 * 32));
    const uint32_t o1 = swz((uint32_t)(row * 128 + u4 * 32 + 16));
    *(uint4*)(base + OFF_A + o0) = make_uint4(h[0], h[1], h[2], h[3]);
    *(uint4*)(base + OFF_A + o1) = make_uint4(h[4], h[5], h[6], h[7]);
#pragma unroll
    for (int p = 0; p < 2; p++) {
        const int slot = p * 256 + t;
        const int n = slot >> 3, u = slot & 7;
        *(uint4*)(base + OFF_B + swz((uint32_t)(n * 128 + u * 16))) = b[p];
    }
}

// ---------------- main kernel ----------------
__global__ __launch_bounds__(THREADS, 2)
void mma_kernel(const float* __restrict__ prev,
                const float* __restrict__ inp,
                float* __restrict__ out) {
    extern __shared__ __align__(1024) char smem[];
    const uint32_t sbse = smem_u32(smem);
    const int t = threadIdx.x;
    const int lane = t & 31, wid = t >> 5;
    const int m0 = blockIdx.x * BM;

    if (t < O_SZ) {
        ((float*)(smem + OFF_BIAS))[t] = g_bias[t];
        ((int*)(smem + OFF_ACT))[t]    = g_act[t];
    }

    // warp tiling: 4 M-groups (16 rows) x 2 N-halves (32 cols)
    const int mg = wid >> 1, nh = wid & 1;
    const int lrow = lane & 7, seg = lane >> 3;
    const int arow = mg * 16 + lrow + ((seg & 1) << 3);
    const int akb0 = (seg & 2) << 3;               // 0 or 16 bytes
    const int browb = lrow + ((seg & 2) << 2);     // +8 for seg>=2
    const int bkb0 = (seg & 1) << 4;               // 0 or 16 bytes

    float acc[4][4];
#pragma unroll
    for (int j = 0; j < 4; j++)
#pragma unroll
        for (int c = 0; c < 4; c++) acc[j][c] = 0.0f;

    float4 A[4];
    uint4  Bv[2];
    load_chunk(0, t, m0, prev, inp, A, Bv);
    store_chunk(smem, t, A, Bv);
    __syncthreads();

    for (int i = 0; i < NCHUNK; i++) {
        if (i + 1 < NCHUNK) load_chunk(i + 1, t, m0, prev, inp, A, Bv);

        const uint32_t st = sbse + (uint32_t)((i & 1) * STAGE_BYTES);
#pragma unroll
        for (int s = 0; s < 4; s++) {
            uint32_t av[4];
            ldsm4(av, st + OFF_A + swz((uint32_t)(arow * 128 + s * 32 + akb0)));
#pragma unroll
            for (int jj = 0; jj < 2; jj++) {
                uint32_t bv[4];
                ldsm4(bv, st + OFF_B +
                          swz((uint32_t)((nh * 32 + jj * 16 + browb) * 128 + s * 32 + bkb0)));
                mma16816(acc[2 * jj],     av, bv[0], bv[1]);
                mma16816(acc[2 * jj + 1], av, bv[2], bv[3]);
            }
        }
        if (i + 1 < NCHUNK)
            store_chunk(smem + ((i + 1) & 1) * STAGE_BYTES, t, A, Bv);
        __syncthreads();
    }

    // ---------------- epilogue ----------------
    const float* sbias = (const float*)(smem + OFF_BIAS);
    const int*   sact  = (const int*)(smem + OFF_ACT);
    const int g = lane >> 2, q = lane & 3;
    const int row0 = m0 + mg * 16 + g;
#pragma unroll
    for (int j = 0; j < 4; j++) {
        const int col = nh * 32 + (j >> 1) * 16 + (j & 1) * 8 + q * 2;
        const float b0 = sbias[col], b1 = sbias[col + 1];
        const int   i0 = sact[col],  i1 = sact[col + 1];
        float2 v0, v1;
        v0.x = activate(acc[j][0] + b0, i0);
        v0.y = activate(acc[j][1] + b1, i1);
        v1.x = activate(acc[j][2] + b0, i0);
        v1.y = activate(acc[j][3] + b1, i1);
        *(float2*)(out + (size_t)row0 * O_SZ + col)       = v0;
        *(float2*)(out + (size_t)(row0 + 8) * O_SZ + col) = v1;
    }
}

extern "C" void kernel_launch(void* const* d_in, const int* in_sizes, int n_in,
                              void* d_out, int out_size) {
    const float* prev = (const float*)d_in[0];   // [16384,1024] f32
    const float* inp  = (const float*)d_in[1];   // [16384,128]  f32
    const float* W    = (const float*)d_in[2];   // [1024,1024]  f32
    const float* bias = (const float*)d_in[3];   // [1024]       f32
    const int*   act  = (const int*)d_in[4];     // [1024]       i32
    float* out = (float*)d_out;                  // [16384,64]   f32

    cudaFuncSetAttribute(mma_kernel,
                         cudaFuncAttributeMaxDynamicSharedMemorySize, SMEM_TOTAL);

    prep_kernel<<<(O_SZ * N_SZ + 255) / 256, 256>>>(W, bias, act);
    mma_kernel<<<B_SZ / BM, THREADS, SMEM_TOTAL>>>(prev, inp, out);
}